// round 6
// baseline (speedup 1.0000x reference)
#include <cuda_runtime.h>
#include <cstdint>

// Problem constants
#define NPROB 2048      // B*S = 8*256
#define DD    128       // feature dim (m = n = 128)
#define NITER 20

// K = (SCALE/eps) * log2(e) = 3000 * log2(e)
#define KCOEF 4328.085098989891f
#define TWOK  8656.170197979782f
#define INVK  2.3105011120474482e-4f
// ot scale: n * SCALE / NPROB = 128*300/2048
#define OTSCALE 18.75f

#define NCOPY   32
#define TH_SKIP 34.0f            // keep terms within 2^-34 of true max
#define PLAN_TH -35.0f           // plan entries below 2^-35 dropped
#define E_TH    -39.0f
#define CTOL    1.0e-5f          // convergence tol on potentials (log2 units)
#define FIX_SCALE 1099511627776.0f // 2^40 fixed-point scale

__device__ unsigned long long g_accum[(size_t)NCOPY * DD * DD];
__device__ float g_ot[DD * DD];

__device__ __forceinline__ float ex2f(float x) {
    float r; asm("ex2.approx.ftz.f32 %0, %1;" : "=f"(r) : "f"(x)); return r;
}
__device__ __forceinline__ float lg2f(float x) {
    float r; asm("lg2.approx.f32 %0, %1;" : "=f"(r) : "f"(x)); return r;
}

__device__ __forceinline__ float warp_max(float v) {
#pragma unroll
    for (int o = 16; o; o >>= 1) v = fmaxf(v, __shfl_xor_sync(0xffffffffu, v, o));
    return v;
}

// Windowed exact two-pass LSE (always valid; no fallback needed).
// arr: 128 x float2{sorted coord, pot}; keys: sorted coords; wmax: max(pot + K*coord^2).
// v_j = twoKc*coord_j + pot_j = K*c^2 - K(c - coord_j)^2 + w_j with c = this lane's coord.
// Returns new potential: -(7 + mx + log2(sum over window of 2^(v - mx))).
__device__ __forceinline__ float lse_win(const float2* __restrict__ arr,
                                         const float* __restrict__ keys,
                                         float c, float twoKc, float wmax) {
    // 1) group g* containing the nearest coords: last group whose first key <= c.
    int gs = 0;
#pragma unroll
    for (int st = 32; st; st >>= 1) {
        int k = gs + st;
        if (k <= 32 && keys[4 * (k - 1)] <= c) gs = k;
    }
    gs = (gs > 0) ? gs - 1 : 0;
    const float4* a4 = reinterpret_cast<const float4*>(arr);
    float4 u = a4[2 * gs], w = a4[2 * gs + 1];
    // v* = max of group g*: a valid LOWER bound on the true max.
    float vst = fmaxf(fmaxf(fmaf(twoKc, u.x, u.y), fmaf(twoKc, u.z, u.w)),
                      fmaxf(fmaf(twoKc, w.x, w.y), fmaf(twoKc, w.z, w.w)));
    // 2) window: any j with v_j >= mx_true - TH satisfies
    //    (c - coord_j)^2 <= c^2 + (wmax + TH - v*)/K  =: r2  (r2 >= TH/K > 0 always)
    float r2 = fmaf(c, c, (wmax + TH_SKIP - vst) * INVK);
    float r = sqrtf(r2);
    float lo = c - r, hi = c + r;
    int glo = 0, ghi = 0;
#pragma unroll
    for (int st = 32; st; st >>= 1) {
        int k = glo + st;
        if (k <= 32 && keys[4 * k - 1] < lo) glo = k;        // group k-1 fully below lo
        int k2 = ghi + st;
        if (k2 <= 32 && keys[4 * (k2 - 1)] <= hi) ghi = k2;  // group k2-1 starts <= hi
    }
    // 3) exact max over window (FMA pipe only)
    float mx = vst;
    for (int g = glo; g < ghi; ++g) {
        float4 uu = a4[2 * g], ww = a4[2 * g + 1];
        mx = fmaxf(mx, fmaxf(fmaf(twoKc, uu.x, uu.y), fmaf(twoKc, uu.z, uu.w)));
        mx = fmaxf(mx, fmaxf(fmaf(twoKc, ww.x, ww.y), fmaf(twoKc, ww.z, ww.w)));
    }
    // 4) exp pass with exact max: s in [1, 128]
    float s0 = 0.f, s1 = 0.f;
    for (int g = glo; g < ghi; ++g) {
        float4 uu = a4[2 * g], ww = a4[2 * g + 1];
        s0 += ex2f(fmaf(twoKc, uu.x, uu.y) - mx);
        s1 += ex2f(fmaf(twoKc, uu.z, uu.w) - mx);
        s0 += ex2f(fmaf(twoKc, ww.x, ww.y) - mx);
        s1 += ex2f(fmaf(twoKc, ww.z, ww.w) - mx);
    }
    return -(7.0f + mx + lg2f(s0 + s1));
}

__global__ void __launch_bounds__(128) sinkhorn_kernel(const float* __restrict__ X,
                                                       const float* __restrict__ Y) {
    __shared__ __align__(16) float2 sx[DD];   // {sorted x, pot a}
    __shared__ __align__(16) float2 sy[DD];   // {sorted y, pot b}
    __shared__ int ox[DD], oy[DD];            // original indices
    __shared__ __align__(16) float kx[DD], ky[DD];   // sorted coords
    __shared__ float wxp[4], wyp[4];          // per-warp maxes of w = pot + K*coord^2

    const int p = blockIdx.x;
    const int t = threadIdx.x;

    kx[t] = X[(size_t)p * DD + t]; ox[t] = t;
    ky[t] = Y[(size_t)p * DD + t]; oy[t] = t;
    if (t < 4) { wxp[t] = 0.f; wyp[t] = 0.f; }   // w == 0 at init (pot = -K*coord^2)
    __syncthreads();

    // Bitonic sort both (kx,ox) and (ky,oy) ascending; index tiebreak.
    for (int k = 2; k <= DD; k <<= 1) {
        for (int j = k >> 1; j > 0; j >>= 1) {
            int prt = t ^ j;
            bool keep_small = ((t < prt) == ((t & k) == 0));
            float mkx = kx[t], pkx = kx[prt];
            int   mix = ox[t], pix = ox[prt];
            float mky = ky[t], pky = ky[prt];
            int   miy = oy[t], piy = oy[prt];
            __syncthreads();
            bool lessx = (mkx < pkx) || (mkx == pkx && mix < pix);
            bool takex = (lessx == keep_small);
            kx[t] = takex ? mkx : pkx;  ox[t] = takex ? mix : pix;
            bool lessy = (mky < pky) || (mky == pky && miy < piy);
            bool takey = (lessy == keep_small);
            ky[t] = takey ? mky : pky;  oy[t] = takey ? miy : piy;
            __syncthreads();
        }
    }

    const float x = kx[t];
    const float y = ky[t];
    const float twoKx = TWOK * x;
    const float twoKy = TWOK * y;
    const float Kx2 = KCOEF * x * x;
    const float Ky2 = KCOEF * y * y;
    float areg = -Kx2;
    float breg = -Ky2;
    sx[t] = make_float2(x, areg);
    sy[t] = make_float2(y, breg);
    __syncthreads();

    for (int it = 0; it < NITER; ++it) {
        // ---- f-update (rows; reduce over sy) ----
        float wmaxy = fmaxf(fmaxf(wyp[0], wyp[1]), fmaxf(wyp[2], wyp[3]));
        float a_new = lse_win(sy, ky, x, twoKx, wmaxy);
        float amov = fabsf(a_new - areg);
        areg = a_new;
        sx[t].y = a_new;
        float wm = warp_max(a_new + Kx2);
        if ((t & 31) == 0) wxp[t >> 5] = wm;
        __syncthreads();

        // ---- g-update (cols; reduce over sx) ----
        float wmaxx = fmaxf(fmaxf(wxp[0], wxp[1]), fmaxf(wxp[2], wxp[3]));
        float b_new = lse_win(sx, kx, y, twoKy, wmaxx);
        float bmov = fabsf(b_new - breg);
        breg = b_new;
        sy[t].y = b_new;
        float wn = warp_max(b_new + Ky2);
        if ((t & 31) == 0) wyp[t >> 5] = wn;

        int moved = (amov > CTOL) || (bmov > CTOL);
        if (!__syncthreads_or(moved)) break;   // fully stalled: later iters are no-ops
    }

    // ---- Plan accumulation: thread t = sorted row t; fixed-point atomic adds ----
    // plan_ij = 2^(a_i + b_j + twoKx_i * y_j); windowed by (x-y)^2 bound.
    {
        const int oi = ox[t];
        unsigned long long* rowp =
            g_accum + (size_t)(p & (NCOPY - 1)) * (DD * DD) + (size_t)oi * DD;
        float wmaxy = fmaxf(fmaxf(wyp[0], wyp[1]), fmaxf(wyp[2], wyp[3]));
        // keep j iff upper bound a + Kx^2 + wmaxy - K(x-y_j)^2 >= PLAN_TH
        float r2 = fmaf(x, x, (wmaxy + areg - PLAN_TH) * INVK);
        if (r2 > 0.f) {
            float r = sqrtf(r2);
            float lo = x - r, hi = x + r;
            int glo = 0, ghi = 0;
#pragma unroll
            for (int st = 32; st; st >>= 1) {
                int c = glo + st;
                if (c <= 32 && ky[4 * c - 1] < lo) glo = c;
                int c2 = ghi + st;
                if (c2 <= 32 && ky[4 * (c2 - 1)] <= hi) ghi = c2;
            }
            const float4* a4 = reinterpret_cast<const float4*>(sy);
            for (int g = glo; g < ghi; ++g) {
                float4 u = a4[2 * g];
                float4 w = a4[2 * g + 1];
                float E0 = fmaf(twoKx, u.x, u.y) + areg;
                float E1 = fmaf(twoKx, u.z, u.w) + areg;
                float E2 = fmaf(twoKx, w.x, w.y) + areg;
                float E3 = fmaf(twoKx, w.z, w.w) + areg;
                if (E0 > E_TH)
                    atomicAdd(rowp + oy[4 * g + 0], __float2ull_rn(ex2f(E0) * FIX_SCALE));
                if (E1 > E_TH)
                    atomicAdd(rowp + oy[4 * g + 1], __float2ull_rn(ex2f(E1) * FIX_SCALE));
                if (E2 > E_TH)
                    atomicAdd(rowp + oy[4 * g + 2], __float2ull_rn(ex2f(E2) * FIX_SCALE));
                if (E3 > E_TH)
                    atomicAdd(rowp + oy[4 * g + 3], __float2ull_rn(ex2f(E3) * FIX_SCALE));
            }
        }
    }
}

__global__ void __launch_bounds__(256) zero_accum_kernel() {
    const int idx = blockIdx.x * 256 + threadIdx.x;
    g_accum[idx] = 0ull;
}

// Sum 32 fixed-point copies (exact integer sum -> deterministic), scale, add delta.
__global__ void __launch_bounds__(256) reduce_b_kernel(const float* __restrict__ delta) {
    const int idx = blockIdx.x * 256 + threadIdx.x;
    unsigned long long tot = 0ull;
#pragma unroll
    for (int c = 0; c < NCOPY; ++c) tot += g_accum[(size_t)c * (DD * DD) + idx];
    g_ot[idx] = (float)((double)tot * ((double)OTSCALE / (double)FIX_SCALE)) + delta[idx];
}

// out[pb..pb+1, :] = X[pb..pb+1, :] @ ot -- 2 rows/block: 1024 blocks (good occ),
// halves g_ot L2 traffic vs 1 row/block.
#define GROWS 2
__global__ void __launch_bounds__(128) gemm_out_kernel(const float* __restrict__ X,
                                                       float* __restrict__ out) {
    __shared__ float xs[GROWS][DD];
    const int pb = blockIdx.x * GROWS;
    const int t = threadIdx.x;
#pragma unroll
    for (int r = 0; r < GROWS; ++r) xs[r][t] = X[(size_t)(pb + r) * DD + t];
    __syncthreads();
    float acc[GROWS];
#pragma unroll
    for (int r = 0; r < GROWS; ++r) acc[r] = 0.f;
#pragma unroll 8
    for (int k = 0; k < DD; ++k) {
        float gv = g_ot[k * DD + t];
#pragma unroll
        for (int r = 0; r < GROWS; ++r) acc[r] = fmaf(xs[r][k], gv, acc[r]);
    }
#pragma unroll
    for (int r = 0; r < GROWS; ++r) out[(size_t)(pb + r) * DD + t] = acc[r];
}

extern "C" void kernel_launch(void* const* d_in, const int* in_sizes, int n_in,
                              void* d_out, int out_size) {
    const float* X = (const float*)d_in[0];      // [8,256,128]
    const float* Y = (const float*)d_in[1];      // [8,256,128]
    const float* delta = (const float*)d_in[2];  // [128,128]
    float* out = (float*)d_out;                  // [8,256,128] float32

    zero_accum_kernel<<<(NCOPY * DD * DD) / 256, 256>>>();
    sinkhorn_kernel<<<NPROB, 128>>>(X, Y);
    reduce_b_kernel<<<(DD * DD) / 256, 256>>>(delta);
    gemm_out_kernel<<<NPROB / GROWS, 128>>>(X, out);
}

// round 7
// speedup vs baseline: 1.4597x; 1.4597x over previous
#include <cuda_runtime.h>
#include <cstdint>

// Problem constants
#define NPROB 2048      // B*S = 8*256
#define DD    128       // feature dim (m = n = 128)
#define NITER 20

// K = (SCALE/eps) * log2(e) = 3000 * log2(e)
#define KCOEF 4328.085098989891f
#define TWOK  8656.170197979782f
#define INVK  2.3105011120474482e-4f
// ot scale: n * SCALE / NPROB = 128*300/2048
#define OTSCALE 18.75f

#define NCOPY   32
#define TH_SKIP 34.0f            // keep terms within 2^-34 of est. max
#define SMIN    2.44140625e-4f   // 2^-12 guard (ties to TH_SKIP drop bound)
#define SMAX    4096.0f          // 2^12 guard
#define PLAN_TH -35.0f           // plan entries below 2^-35 dropped
#define E_TH    -39.0f
#define CTOL    1.0e-5f          // convergence tol on potentials (log2 units)
#define FIX_SCALE 1099511627776.0f // 2^40 fixed-point scale

__device__ unsigned long long g_accum[(size_t)NCOPY * DD * DD];
__device__ float g_ot[DD * DD];

__device__ __forceinline__ float ex2f(float x) {
    float r; asm("ex2.approx.ftz.f32 %0, %1;" : "=f"(r) : "f"(x)); return r;
}
__device__ __forceinline__ float lg2f(float x) {
    float r; asm("lg2.approx.f32 %0, %1;" : "=f"(r) : "f"(x)); return r;
}

__device__ __forceinline__ float warp_max(float v) {
#pragma unroll
    for (int o = 16; o; o >>= 1) v = fmaxf(v, __shfl_xor_sync(0xffffffffu, v, o));
    return v;
}

// Full two-pass LSE sweep over 128 float2{coord, pot} entries (exact fallback,
// warp-uniform call). v_j = twoKc*coord_j + pot_j.
__device__ __forceinline__ float lse_full(const float2* __restrict__ arr, float twoKc) {
    const float4* a4 = reinterpret_cast<const float4*>(arr);
    float m0 = -1e30f, m1 = -1e30f, m2 = -1e30f, m3 = -1e30f;
#pragma unroll 8
    for (int q = 0; q < DD / 4; ++q) {
        float4 u = a4[2 * q];
        float4 w = a4[2 * q + 1];
        m0 = fmaxf(m0, fmaf(twoKc, u.x, u.y));
        m1 = fmaxf(m1, fmaf(twoKc, u.z, u.w));
        m2 = fmaxf(m2, fmaf(twoKc, w.x, w.y));
        m3 = fmaxf(m3, fmaf(twoKc, w.z, w.w));
    }
    float mx = fmaxf(fmaxf(m0, m1), fmaxf(m2, m3));
    float s0 = 0.f, s1 = 0.f, s2 = 0.f, s3 = 0.f;
#pragma unroll 8
    for (int q = 0; q < DD / 4; ++q) {
        float4 u = a4[2 * q];
        float4 w = a4[2 * q + 1];
        s0 += ex2f(fmaf(twoKc, u.x, u.y) - mx);
        s1 += ex2f(fmaf(twoKc, u.z, u.w) - mx);
        s2 += ex2f(fmaf(twoKc, w.x, w.y) - mx);
        s3 += ex2f(fmaf(twoKc, w.z, w.w) - mx);
    }
    float s = (s0 + s1) + (s2 + s3);
    return -(7.0f + mx + lg2f(s));
}

// Warp-union window: per-lane [lo,hi] (NaN lanes drop out of the min/max union),
// then ONE uniform binary search + ONE uniform loop over union groups.
// Returns per-lane s = sum over union window of 2^(v_j - mx_est).
__device__ __forceinline__ float union_sum(const float2* __restrict__ arr,
                                           const float* __restrict__ keys,
                                           float twoKc, float mx_est,
                                           float lo, float hi) {
#pragma unroll
    for (int o = 16; o; o >>= 1) {
        lo = fminf(lo, __shfl_xor_sync(0xffffffffu, lo, o));
        hi = fmaxf(hi, __shfl_xor_sync(0xffffffffu, hi, o));
    }
    int Glo = 0, Ghi = 0;
#pragma unroll
    for (int st = 32; st; st >>= 1) {
        int k = Glo + st;
        if (k <= 32 && keys[4 * k - 1] < lo) Glo = k;        // group k-1 fully below lo
        int k2 = Ghi + st;
        if (k2 <= 32 && keys[4 * (k2 - 1)] <= hi) Ghi = k2;  // group k2-1 starts <= hi
    }
    const float4* a4 = reinterpret_cast<const float4*>(arr);
    float s0 = 0.f, s1 = 0.f;
    for (int g = Glo; g < Ghi; ++g) {     // warp-uniform trip count, broadcast loads
        float4 u = a4[2 * g];
        float4 w = a4[2 * g + 1];
        s0 += ex2f(fmaf(twoKc, u.x, u.y) - mx_est);
        s1 += ex2f(fmaf(twoKc, u.z, u.w) - mx_est);
        s0 += ex2f(fmaf(twoKc, w.x, w.y) - mx_est);
        s1 += ex2f(fmaf(twoKc, w.z, w.w) - mx_est);
    }
    return s0 + s1;
}

__global__ void __launch_bounds__(128) sinkhorn_kernel(const float* __restrict__ X,
                                                       const float* __restrict__ Y) {
    __shared__ __align__(16) float2 sx[DD];   // {sorted x, pot a}
    __shared__ __align__(16) float2 sy[DD];   // {sorted y, pot b}
    __shared__ int ox[DD], oy[DD];            // original indices
    __shared__ __align__(16) float kx[DD], ky[DD];   // sorted coords
    __shared__ float wxp[4], wyp[4];          // per-warp maxes of w = pot + K*coord^2

    const int p = blockIdx.x;
    const int t = threadIdx.x;

    kx[t] = X[(size_t)p * DD + t]; ox[t] = t;
    ky[t] = Y[(size_t)p * DD + t]; oy[t] = t;
    if (t < 4) { wxp[t] = 0.f; wyp[t] = 0.f; }   // w == 0 at init (pot = -K*coord^2)
    __syncthreads();

    // Bitonic sort both (kx,ox) and (ky,oy) ascending; index tiebreak.
    for (int k = 2; k <= DD; k <<= 1) {
        for (int j = k >> 1; j > 0; j >>= 1) {
            int prt = t ^ j;
            bool keep_small = ((t < prt) == ((t & k) == 0));
            float mkx = kx[t], pkx = kx[prt];
            int   mix = ox[t], pix = ox[prt];
            float mky = ky[t], pky = ky[prt];
            int   miy = oy[t], piy = oy[prt];
            __syncthreads();
            bool lessx = (mkx < pkx) || (mkx == pkx && mix < pix);
            bool takex = (lessx == keep_small);
            kx[t] = takex ? mkx : pkx;  ox[t] = takex ? mix : pix;
            bool lessy = (mky < pky) || (mky == pky && miy < piy);
            bool takey = (lessy == keep_small);
            ky[t] = takey ? mky : pky;  oy[t] = takey ? miy : piy;
            __syncthreads();
        }
    }

    const float x = kx[t];
    const float y = ky[t];
    const float twoKx = TWOK * x;
    const float twoKy = TWOK * y;
    const float Kx2 = KCOEF * x * x;
    const float Ky2 = KCOEF * y * y;
    float areg = -Kx2;
    float breg = -Ky2;
    sx[t] = make_float2(x, areg);
    sy[t] = make_float2(y, breg);
    __syncthreads();

    for (int it = 0; it < NITER; ++it) {
        // ---- f-update (rows; reduce over sy) ----
        {
            float wmaxy = fmaxf(fmaxf(wyp[0], wyp[1]), fmaxf(wyp[2], wyp[3]));
            float mx_est = -7.0f - areg;
            // keep j iff (x - y_j)^2 < r2 (upper bound vs stale-max threshold)
            float r2 = fmaf(x, x, (wmaxy + 7.0f + TH_SKIP + areg) * INVK);
            float r = sqrtf(r2);               // NaN if r2<0 -> lane exits union
            float s = union_sum(sy, ky, twoKx, mx_est, x - r, x + r);
            float a_new = -(7.0f + mx_est + lg2f(s));
            bool bad = !(s >= SMIN && s <= SMAX);
            if (__any_sync(0xffffffffu, bad)) a_new = lse_full(sy, twoKx);
            float amov = fabsf(a_new - areg);
            areg = a_new;
            sx[t].y = a_new;
            float wm = warp_max(a_new + Kx2);
            if ((t & 31) == 0) wxp[t >> 5] = wm;
            __syncthreads();

            // ---- g-update (cols; reduce over sx) ----
            float wmaxx = fmaxf(fmaxf(wxp[0], wxp[1]), fmaxf(wxp[2], wxp[3]));
            float my_est = -7.0f - breg;
            float q2 = fmaf(y, y, (wmaxx + 7.0f + TH_SKIP + breg) * INVK);
            float q = sqrtf(q2);
            float sb = union_sum(sx, kx, twoKy, my_est, y - q, y + q);
            float b_new = -(7.0f + my_est + lg2f(sb));
            bool badb = !(sb >= SMIN && sb <= SMAX);
            if (__any_sync(0xffffffffu, badb)) b_new = lse_full(sx, twoKy);
            float bmov = fabsf(b_new - breg);
            breg = b_new;
            sy[t].y = b_new;
            float wn = warp_max(b_new + Ky2);
            if ((t & 31) == 0) wyp[t >> 5] = wn;

            int moved = (amov > CTOL) || (bmov > CTOL);
            if (!__syncthreads_or(moved)) break;   // fully stalled: rest are no-ops
        }
    }

    // ---- Plan accumulation: thread t = sorted row t; fixed-point atomic adds ----
    // plan_ij = 2^(a_i + b_j + twoKx_i * y_j); union window, uniform loop.
    {
        const int oi = ox[t];
        unsigned long long* rowp =
            g_accum + (size_t)(p & (NCOPY - 1)) * (DD * DD) + (size_t)oi * DD;
        float wmaxy = fmaxf(fmaxf(wyp[0], wyp[1]), fmaxf(wyp[2], wyp[3]));
        // keep j iff a + Kx^2 + wmaxy - K(x-y_j)^2 >= PLAN_TH
        float r2 = fmaf(x, x, (wmaxy + areg - PLAN_TH) * INVK);
        float r = sqrtf(r2);                   // NaN lanes drop from union
        float lo = x - r, hi = x + r;
#pragma unroll
        for (int o = 16; o; o >>= 1) {
            lo = fminf(lo, __shfl_xor_sync(0xffffffffu, lo, o));
            hi = fmaxf(hi, __shfl_xor_sync(0xffffffffu, hi, o));
        }
        int Glo = 0, Ghi = 0;
#pragma unroll
        for (int st = 32; st; st >>= 1) {
            int c = Glo + st;
            if (c <= 32 && ky[4 * c - 1] < lo) Glo = c;
            int c2 = Ghi + st;
            if (c2 <= 32 && ky[4 * (c2 - 1)] <= hi) Ghi = c2;
        }
        const float4* a4 = reinterpret_cast<const float4*>(sy);
        for (int g = Glo; g < Ghi; ++g) {      // uniform loop; predicated atomics
            float4 u = a4[2 * g];
            float4 w = a4[2 * g + 1];
            float E0 = fmaf(twoKx, u.x, u.y) + areg;
            float E1 = fmaf(twoKx, u.z, u.w) + areg;
            float E2 = fmaf(twoKx, w.x, w.y) + areg;
            float E3 = fmaf(twoKx, w.z, w.w) + areg;
            if (E0 > E_TH)
                atomicAdd(rowp + oy[4 * g + 0], __float2ull_rn(ex2f(E0) * FIX_SCALE));
            if (E1 > E_TH)
                atomicAdd(rowp + oy[4 * g + 1], __float2ull_rn(ex2f(E1) * FIX_SCALE));
            if (E2 > E_TH)
                atomicAdd(rowp + oy[4 * g + 2], __float2ull_rn(ex2f(E2) * FIX_SCALE));
            if (E3 > E_TH)
                atomicAdd(rowp + oy[4 * g + 3], __float2ull_rn(ex2f(E3) * FIX_SCALE));
        }
    }
}

__global__ void __launch_bounds__(256) zero_accum_kernel() {
    const int idx = blockIdx.x * 256 + threadIdx.x;
    g_accum[idx] = 0ull;
}

// Sum 32 fixed-point copies (exact integer sum -> deterministic), scale, add delta.
__global__ void __launch_bounds__(256) reduce_b_kernel(const float* __restrict__ delta) {
    const int idx = blockIdx.x * 256 + threadIdx.x;
    unsigned long long tot = 0ull;
#pragma unroll
    for (int c = 0; c < NCOPY; ++c) tot += g_accum[(size_t)c * (DD * DD) + idx];
    g_ot[idx] = (float)((double)tot * ((double)OTSCALE / (double)FIX_SCALE)) + delta[idx];
}

// out[pb..pb+3, :] = X[pb..pb+3, :] @ ot -- 4 rows/block: grid 512, g_ot L2
// traffic 32MB, occupancy preserved.
#define GROWS 4
__global__ void __launch_bounds__(128) gemm_out_kernel(const float* __restrict__ X,
                                                       float* __restrict__ out) {
    __shared__ float xs[GROWS][DD];
    const int pb = blockIdx.x * GROWS;
    const int t = threadIdx.x;
#pragma unroll
    for (int r = 0; r < GROWS; ++r) xs[r][t] = X[(size_t)(pb + r) * DD + t];
    __syncthreads();
    float acc[GROWS];
#pragma unroll
    for (int r = 0; r < GROWS; ++r) acc[r] = 0.f;
#pragma unroll 4
    for (int k = 0; k < DD; ++k) {
        float gv = g_ot[k * DD + t];
#pragma unroll
        for (int r = 0; r < GROWS; ++r) acc[r] = fmaf(xs[r][k], gv, acc[r]);
    }
#pragma unroll
    for (int r = 0; r < GROWS; ++r) out[(size_t)(pb + r) * DD + t] = acc[r];
}

extern "C" void kernel_launch(void* const* d_in, const int* in_sizes, int n_in,
                              void* d_out, int out_size) {
    const float* X = (const float*)d_in[0];      // [8,256,128]
    const float* Y = (const float*)d_in[1];      // [8,256,128]
    const float* delta = (const float*)d_in[2];  // [128,128]
    float* out = (float*)d_out;                  // [8,256,128] float32

    zero_accum_kernel<<<(NCOPY * DD * DD) / 256, 256>>>();
    sinkhorn_kernel<<<NPROB, 128>>>(X, Y);
    reduce_b_kernel<<<(DD * DD) / 256, 256>>>(delta);
    gemm_out_kernel<<<NPROB / GROWS, 128>>>(X, out);
}